// round 1
// baseline (speedup 1.0000x reference)
#include <cuda_runtime.h>
#include <cstdint>

#define W_TOT 8192
#define BATCH 4
#define CH 256
#define HEADS 4
#define HD 64
#define KATT 7
#define PADR 3

// ---------------- scratch: q,k,v planes [3][B][256][W] ----------------
__device__ float g_qkv[3ULL * BATCH * CH * W_TOT];

// ---------------- packed f32x2 helpers ----------------
__device__ __forceinline__ unsigned long long pk2(float lo, float hi) {
    unsigned long long r;
    asm("mov.b64 %0, {%1, %2};" : "=l"(r) : "f"(lo), "f"(hi));
    return r;
}
__device__ __forceinline__ void upk2(unsigned long long v, float &lo, float &hi) {
    asm("mov.b64 {%0, %1}, %2;" : "=f"(lo), "=f"(hi) : "l"(v));
}
__device__ __forceinline__ unsigned long long ffma2(unsigned long long a,
                                                    unsigned long long b,
                                                    unsigned long long c) {
    unsigned long long d;
    asm("fma.rn.f32x2 %0, %1, %2, %3;" : "=l"(d) : "l"(a), "l"(b), "l"(c));
    return d;
}

// ---------------- GEMM: qkv = W @ x + bias ----------------
// per block: BM=128 rows of one of {w1,w2,w3}, BN=128 columns of x[b]
#define BM 128
#define BN 128
#define BK 16
#define TM 8
#define TN 8

__global__ __launch_bounds__(256) void gemm_qkv_kernel(
    const float* __restrict__ x,
    const float* __restrict__ w1, const float* __restrict__ b1,
    const float* __restrict__ w2, const float* __restrict__ b2,
    const float* __restrict__ w3, const float* __restrict__ b3)
{
    const int bt = blockIdx.z;          // batch
    const int mt = blockIdx.y;          // 0..5
    const int n0 = blockIdx.x * BN;
    const int t  = mt >> 1;             // 0=q,1=k,2=v
    const int m0 = (mt & 1) * BM;       // row offset within 256

    const float* wA   = (t == 0) ? w1 : (t == 1) ? w2 : w3;
    const float* bias = (t == 0) ? b1 : (t == 1) ? b2 : b3;
    const float* X    = x + (size_t)bt * CH * W_TOT;
    float* out = g_qkv + ((size_t)t * BATCH + bt) * CH * W_TOT;

    __shared__ float As[BK][BM];   // transposed A tile
    __shared__ float Bs[BK][BN];

    const int tid = threadIdx.x;
    const int tx = tid & 15;       // 0..15
    const int ty = tid >> 4;       // 0..15

    unsigned long long acc2[TM][TN / 2];
#pragma unroll
    for (int i = 0; i < TM; i++)
#pragma unroll
        for (int j = 0; j < TN / 2; j++) acc2[i][j] = 0ULL;

    for (int k0 = 0; k0 < CH; k0 += BK) {
        // load A tile (128 x 16), store transposed
#pragma unroll
        for (int i = tid; i < 512; i += 256) {
            int r = i >> 2, c4 = i & 3;
            float4 v = *(const float4*)(wA + (size_t)(m0 + r) * CH + k0 + c4 * 4);
            As[c4 * 4 + 0][r] = v.x;
            As[c4 * 4 + 1][r] = v.y;
            As[c4 * 4 + 2][r] = v.z;
            As[c4 * 4 + 3][r] = v.w;
        }
        // load B tile (16 x 128)
#pragma unroll
        for (int i = tid; i < 512; i += 256) {
            int r = i >> 5, c4 = i & 31;
            float4 v = *(const float4*)(X + (size_t)(k0 + r) * W_TOT + n0 + c4 * 4);
            *(float4*)&Bs[r][c4 * 4] = v;
        }
        __syncthreads();

#pragma unroll
        for (int kk = 0; kk < BK; kk++) {
            float4 a0 = *(float4*)&As[kk][ty * TM];
            float4 a1 = *(float4*)&As[kk][ty * TM + 4];
            float4 bq0 = *(float4*)&Bs[kk][tx * TN];
            float4 bq1 = *(float4*)&Bs[kk][tx * TN + 4];
            unsigned long long bb[4];
            bb[0] = pk2(bq0.x, bq0.y);
            bb[1] = pk2(bq0.z, bq0.w);
            bb[2] = pk2(bq1.x, bq1.y);
            bb[3] = pk2(bq1.z, bq1.w);
            float av[TM] = {a0.x, a0.y, a0.z, a0.w, a1.x, a1.y, a1.z, a1.w};
#pragma unroll
            for (int i = 0; i < TM; i++) {
                unsigned long long ad = pk2(av[i], av[i]);
#pragma unroll
                for (int j = 0; j < TN / 2; j++)
                    acc2[i][j] = ffma2(ad, bb[j], acc2[i][j]);
            }
        }
        __syncthreads();
    }

    // epilogue: add bias, store
#pragma unroll
    for (int i = 0; i < TM; i++) {
        int r = m0 + ty * TM + i;
        float bv = bias[r];
        float o[TN];
#pragma unroll
        for (int j = 0; j < TN / 2; j++) {
            float lo, hi;
            upk2(acc2[i][j], lo, hi);
            o[2 * j] = lo + bv;
            o[2 * j + 1] = hi + bv;
        }
        float* op = out + (size_t)r * W_TOT + n0 + tx * TN;
        *(float4*)op       = make_float4(o[0], o[1], o[2], o[3]);
        *(float4*)(op + 4) = make_float4(o[4], o[5], o[6], o[7]);
    }
}

// ---------------- fused attention + conv epilogue ----------------
#define TW 32
#define KS 39   // 32 + 6 halo, +1 pad

__global__ __launch_bounds__(128) void epilogue_kernel(
    const float* __restrict__ wp,
    const float* __restrict__ fc_w,
    const float* __restrict__ dep_w, const float* __restrict__ dep_b,
    const float* __restrict__ rate1p, const float* __restrict__ rate2p,
    float* __restrict__ out)
{
    const int b  = blockIdx.y;
    const int w0 = blockIdx.x * TW;
    const size_t plane = (size_t)BATCH * CH * W_TOT;
    const float* qg = g_qkv + (size_t)b * CH * W_TOT;
    const float* kg = qg + plane;
    const float* vg = qg + 2 * plane;

    extern __shared__ float sm[];
    float* qs = sm;                 // [256][TW]
    float* ks = qs + CH * TW;       // [256][KS]
    float* vs = ks + CH * KS;       // [256][KS]

    const int tid = threadIdx.x;    // 128

    // stage q tile
    for (int i = tid; i < CH * (TW / 4); i += 128) {
        int c = i / (TW / 4), j4 = i % (TW / 4);
        float4 v = *(const float4*)(qg + (size_t)c * W_TOT + w0 + j4 * 4);
        *(float4*)&qs[c * TW + j4 * 4] = v;
    }
    // stage k,v tiles with halo (reflection applied at load)
    for (int i = tid; i < CH * (TW + 6); i += 128) {
        int c = i / (TW + 6), j = i % (TW + 6);
        int gp = w0 - PADR + j;
        gp = gp < 0 ? -gp : (gp >= W_TOT ? 2 * W_TOT - 2 - gp : gp);
        ks[c * KS + j] = kg[(size_t)c * W_TOT + gp];
        vs[c * KS + j] = vg[(size_t)c * W_TOT + gp];
    }
    __syncthreads();

    const int wl = tid & (TW - 1);
    const int h  = tid / TW;
    const int w  = w0 + wl;
    const float inv = 2.0f / (float)(W_TOT - 1);
    const float locw = -1.0f + inv * (float)w;

    // q registers (scaled) and q.wp
    float qreg[HD];
    float qwp = 0.0f;
#pragma unroll
    for (int d = 0; d < HD; d++) {
        float qv = qs[(h * HD + d) * TW + wl] * 0.125f;
        qreg[d] = qv;
        qwp += qv * wp[d];
    }

    // logits
    float logit[KATT];
#pragma unroll
    for (int k = 0; k < KATT; k++) {
        int pos = w + k - PADR;
        int pr = pos < 0 ? -pos : (pos >= W_TOT ? 2 * W_TOT - 2 - pos : pos);
        float locp = -1.0f + inv * (float)pr;
        const float* kp = &ks[h * HD * KS + wl + k];
        float s = 0.0f;
#pragma unroll
        for (int d = 0; d < HD; d++) s += qreg[d] * kp[d * KS];
        logit[k] = s + qwp * (locw - locp);
    }

    // softmax over window
    float m = logit[0];
#pragma unroll
    for (int k = 1; k < KATT; k++) m = fmaxf(m, logit[k]);
    float att[KATT];
    float ssum = 0.0f;
#pragma unroll
    for (int k = 0; k < KATT; k++) { att[k] = __expf(logit[k] - m); ssum += att[k]; }
    float rs = 1.0f / ssum;
#pragma unroll
    for (int k = 0; k < KATT; k++) att[k] *= rs;

    const float r1 = rate1p[0], r2 = rate2p[0];

    // conv branch: f_conv[d'] for d' = h*16 + j  (channels this thread writes)
    float fcw[12];
#pragma unroll
    for (int i = 0; i < 12; i++) fcw[i] = fc_w[i];
    float fv[16];
#pragma unroll
    for (int j = 0; j < 16; j++) {
        int dd = h * 16 + j;
        float f = 0.0f;
#pragma unroll
        for (int hh = 0; hh < HEADS; hh++) {
            f += fcw[hh]     * qs[(hh * HD + dd) * TW + wl];
            f += fcw[4 + hh] * ks[(hh * HD + dd) * KS + wl + PADR];
            f += fcw[8 + hh] * vs[(hh * HD + dd) * KS + wl + PADR];
        }
        fv[j] = f;
    }

    float* outp = out + (size_t)b * CH * W_TOT + w;
#pragma unroll
    for (int d = 0; d < HD; d++) {
        int c = h * HD + d;
        const float* vp = &vs[c * KS + wl];
        float oa = 0.0f;
#pragma unroll
        for (int k = 0; k < KATT; k++) oa += att[k] * vp[k];
        float ocv = dep_w[c] * fv[d >> 2] + dep_b[c];
        outp[(size_t)c * W_TOT] = r1 * oa + r2 * ocv;
    }
}

// ---------------- launch ----------------
extern "C" void kernel_launch(void* const* d_in, const int* in_sizes, int n_in,
                              void* d_out, int out_size)
{
    const float* x     = (const float*)d_in[0];
    const float* w1    = (const float*)d_in[1];
    const float* b1    = (const float*)d_in[2];
    const float* w2    = (const float*)d_in[3];
    const float* b2    = (const float*)d_in[4];
    const float* w3    = (const float*)d_in[5];
    const float* b3    = (const float*)d_in[6];
    const float* wp    = (const float*)d_in[7];
    // d_in[8] = bp : cancels analytically (pe difference), unused
    const float* fc_w  = (const float*)d_in[9];
    const float* dep_w = (const float*)d_in[10];
    const float* dep_b = (const float*)d_in[11];
    const float* rate1 = (const float*)d_in[12];
    const float* rate2 = (const float*)d_in[13];
    float* out = (float*)d_out;

    // GEMM: qkv
    dim3 ggrid(W_TOT / BN, 6, BATCH);
    gemm_qkv_kernel<<<ggrid, 256>>>(x, w1, b1, w2, b2, w3, b3);

    // fused attention + conv epilogue
    const int smem_bytes = (CH * TW + 2 * CH * KS) * (int)sizeof(float); // 112640
    cudaFuncSetAttribute(epilogue_kernel,
                         cudaFuncAttributeMaxDynamicSharedMemorySize, smem_bytes);
    dim3 egrid(W_TOT / TW, BATCH);
    epilogue_kernel<<<egrid, 128, smem_bytes>>>(wp, fc_w, dep_w, dep_b,
                                                rate1, rate2, out);
}

// round 4
// speedup vs baseline: 2.6825x; 2.6825x over previous
#include <cuda_runtime.h>
#include <cuda_bf16.h>
#include <cstdint>

#define W_TOT 8192
#define BATCH 4
#define CH 256
#define HEADS 4
#define HD 64
#define KATT 7
#define PADR 3
#define MROWS 768

// ---------------- scratch ----------------
__device__ float         g_qkv[3ULL * BATCH * CH * W_TOT];          // fp32 q,k,v planes
__device__ __nv_bfloat16 g_xt_hi[(size_t)BATCH * W_TOT * CH];       // x^T hi [b][w][c]
__device__ __nv_bfloat16 g_xt_lo[(size_t)BATCH * W_TOT * CH];       // x^T lo
__device__ __nv_bfloat16 g_a_hi[MROWS * CH];                        // stacked w1,w2,w3 hi
__device__ __nv_bfloat16 g_a_lo[MROWS * CH];
__device__ float         g_f[(size_t)BATCH * HD * W_TOT];           // conv-branch f

// ---------------- helpers ----------------
__device__ __forceinline__ uint32_t smem_to_u32(const void* p) {
    uint32_t a;
    asm("{ .reg .u64 t; cvta.to.shared.u64 t, %1; cvt.u32.u64 %0, t; }" : "=r"(a) : "l"(p));
    return a;
}
__device__ __forceinline__ void cp_async16(uint32_t saddr, const void* g) {
    asm volatile("cp.async.cg.shared.global [%0], [%1], 16;" :: "r"(saddr), "l"(g));
}
#define CP_COMMIT() asm volatile("cp.async.commit_group;" ::: "memory")
#define CP_WAIT(n)  asm volatile("cp.async.wait_group %0;" :: "n"(n) : "memory")

__device__ __forceinline__ void ldsm4(uint32_t* r, uint32_t addr) {
    asm volatile("ldmatrix.sync.aligned.m8n8.x4.shared.b16 {%0,%1,%2,%3}, [%4];"
                 : "=r"(r[0]), "=r"(r[1]), "=r"(r[2]), "=r"(r[3]) : "r"(addr));
}
__device__ __forceinline__ void mma16816(float* d, const uint32_t* a, const uint32_t* b) {
    asm volatile(
        "mma.sync.aligned.m16n8k16.row.col.f32.bf16.bf16.f32 "
        "{%0,%1,%2,%3}, {%4,%5,%6,%7}, {%8,%9}, {%0,%1,%2,%3};"
        : "+f"(d[0]), "+f"(d[1]), "+f"(d[2]), "+f"(d[3])
        : "r"(a[0]), "r"(a[1]), "r"(a[2]), "r"(a[3]), "r"(b[0]), "r"(b[1]));
}

// ---------------- prep: transpose + hi/lo split of x ----------------
__global__ void transpose_split(const float* __restrict__ x) {
    __shared__ float tile[32][33];
    const int b = blockIdx.z, c0 = blockIdx.y * 32, w0 = blockIdx.x * 32;
    const int tx = threadIdx.x, ty = threadIdx.y;
    const float* xp = x + ((size_t)b * CH + c0) * W_TOT + w0;
#pragma unroll
    for (int i = 0; i < 4; i++)
        tile[ty + i * 8][tx] = xp[(size_t)(ty + i * 8) * W_TOT + tx];
    __syncthreads();
    const size_t ob = ((size_t)b * W_TOT + w0) * CH + c0;
#pragma unroll
    for (int i = 0; i < 4; i++) {
        int r = ty + i * 8;
        float v = tile[tx][r];
        __nv_bfloat16 hi = __float2bfloat16(v);
        float lo = v - __bfloat162float(hi);
        g_xt_hi[ob + (size_t)r * CH + tx] = hi;
        g_xt_lo[ob + (size_t)r * CH + tx] = __float2bfloat16(lo);
    }
}

// ---------------- prep: split weights ----------------
__global__ void convert_w(const float* __restrict__ w1, const float* __restrict__ w2,
                          const float* __restrict__ w3) {
    const int m = blockIdx.x, k = threadIdx.x;
    const float* src = (m < 256) ? w1 : (m < 512) ? w2 : w3;
    float v = src[(size_t)(m & 255) * CH + k];
    __nv_bfloat16 hi = __float2bfloat16(v);
    float lo = v - __bfloat162float(hi);
    g_a_hi[(size_t)m * CH + k] = hi;
    g_a_lo[(size_t)m * CH + k] = __float2bfloat16(lo);
}

// ---------------- HMMA GEMM: qkv = W @ x + bias ----------------
// CTA tile 128x128, K-chunks of 64 bf16 (128B rows, SW128 swizzle),
// extended K: pairs (Ah,Bh), (Ah,Bl), (Al,Bh) -> 12 chunks total.
#define GEMM_SMEM (2 * 32768)
#define NCHUNK 12

__device__ __forceinline__ void stage_tile(uint32_t sA, uint32_t sB,
                                           const __nv_bfloat16* __restrict__ Ag,
                                           const __nv_bfloat16* __restrict__ Bg,
                                           int k0, int tid) {
#pragma unroll
    for (int i = tid; i < 1024; i += 256) {          // A: 128 rows x 8 chunks
        int r = i >> 3, c = i & 7;
        uint32_t off = (uint32_t)(r * 128) + (uint32_t)((c * 16) ^ ((r & 7) << 4));
        cp_async16(sA + off, Ag + (size_t)r * CH + k0 + c * 8);
    }
#pragma unroll
    for (int i = tid; i < 1024; i += 256) {          // B: 128 rows x 8 chunks
        int r = i >> 3, c = i & 7;
        uint32_t off = (uint32_t)(r * 128) + (uint32_t)((c * 16) ^ ((r & 7) << 4));
        cp_async16(sB + off, Bg + (size_t)r * CH + k0 + c * 8);
    }
}

__global__ __launch_bounds__(256) void gemm_mma(const float* __restrict__ b1,
                                                const float* __restrict__ b2,
                                                const float* __restrict__ b3) {
    extern __shared__ char smem[];
    const uint32_t sb = smem_to_u32(smem);
    const int tid = threadIdx.x, wid = tid >> 5, lane = tid & 31;
    const int n0 = blockIdx.x * 128, m0 = blockIdx.y * 128, bb = blockIdx.z;
    const int mw = (wid & 1) * 64;      // warp M offset
    const int nw = (wid >> 1) * 32;     // warp N offset

    const __nv_bfloat16* Ahp = g_a_hi + (size_t)m0 * CH;
    const __nv_bfloat16* Alp = g_a_lo + (size_t)m0 * CH;
    const __nv_bfloat16* Bhp = g_xt_hi + ((size_t)bb * W_TOT + n0) * CH;
    const __nv_bfloat16* Blp = g_xt_lo + ((size_t)bb * W_TOT + n0) * CH;

    float acc[4][4][4];
#pragma unroll
    for (int i = 0; i < 4; i++)
#pragma unroll
        for (int j = 0; j < 4; j++)
#pragma unroll
            for (int e = 0; e < 4; e++) acc[i][j][e] = 0.f;

    // precomputed ldmatrix lane addressing (within-tile offsets)
    const int l15 = lane & 15, lhi = lane >> 4;
    const uint32_t xorv = (uint32_t)((lane & 7) << 4);
    uint32_t aRow[4], bRow[2];
#pragma unroll
    for (int mi = 0; mi < 4; mi++) aRow[mi] = (uint32_t)((mw + mi * 16 + l15) * 128);
#pragma unroll
    for (int jj = 0; jj < 2; jj++)
        bRow[jj] = (uint32_t)((nw + jj * 16 + (lane & 7) + ((lane >> 4) << 3)) * 128);
    const uint32_t aKb[4] = {
        (uint32_t)((0 * 32 + lhi * 16) ^ xorv), (uint32_t)((1 * 32 + lhi * 16) ^ xorv),
        (uint32_t)((2 * 32 + lhi * 16) ^ xorv), (uint32_t)((3 * 32 + lhi * 16) ^ xorv)};
    const uint32_t bKb[4] = {
        (uint32_t)((0 * 32 + (((lane >> 3) & 1) << 4)) ^ xorv),
        (uint32_t)((1 * 32 + (((lane >> 3) & 1) << 4)) ^ xorv),
        (uint32_t)((2 * 32 + (((lane >> 3) & 1) << 4)) ^ xorv),
        (uint32_t)((3 * 32 + (((lane >> 3) & 1) << 4)) ^ xorv)};

    // chunk -> (A,B) source
    auto srcA = [&](int ck) -> const __nv_bfloat16* { return (ck < 8) ? Ahp : Alp; };
    auto srcB = [&](int ck) -> const __nv_bfloat16* {
        int p = ck >> 2;
        return (p == 1) ? Blp : Bhp;
    };

    // prologue: stage chunk 0 into buffer 0
    stage_tile(sb, sb + 16384, srcA(0), srcB(0), 0, tid);
    CP_COMMIT();

    for (int ck = 0; ck < NCHUNK; ck++) {
        if (ck + 1 < NCHUNK) {
            const uint32_t bo = (uint32_t)(((ck + 1) & 1) * 32768);
            stage_tile(sb + bo, sb + bo + 16384, srcA(ck + 1), srcB(ck + 1),
                       ((ck + 1) & 3) * 64, tid);
            CP_COMMIT();
            CP_WAIT(1);
        } else {
            CP_WAIT(0);
        }
        __syncthreads();

        const uint32_t sA = sb + (uint32_t)((ck & 1) * 32768);
        const uint32_t sB = sA + 16384;
#pragma unroll
        for (int kk = 0; kk < 4; kk++) {
            uint32_t af[4][4], bf[2][4];
#pragma unroll
            for (int mi = 0; mi < 4; mi++) ldsm4(af[mi], sA + aRow[mi] + aKb[kk]);
#pragma unroll
            for (int jj = 0; jj < 2; jj++) ldsm4(bf[jj], sB + bRow[jj] + bKb[kk]);
#pragma unroll
            for (int mi = 0; mi < 4; mi++) {
#pragma unroll
                for (int jj = 0; jj < 2; jj++) {
                    mma16816(acc[mi][2 * jj],     af[mi], &bf[jj][0]);
                    mma16816(acc[mi][2 * jj + 1], af[mi], &bf[jj][2]);
                }
            }
        }
        __syncthreads();
    }

    // epilogue: bias add + fp32 store to g_qkv
    const int t_sel = m0 >> 8;
    const float* bp = (t_sel == 0) ? b1 : (t_sel == 1) ? b2 : b3;
#pragma unroll
    for (int mi = 0; mi < 4; mi++) {
        const int mloc = m0 + mw + mi * 16 + (lane >> 2);
        const int c0r = mloc & 255;
        const float bv0 = __ldg(&bp[c0r]);
        const float bv1 = __ldg(&bp[c0r + 8]);
        float* op0 = g_qkv + (((size_t)t_sel * BATCH + bb) * CH + c0r) * W_TOT + n0;
        float* op1 = op0 + (size_t)8 * W_TOT;
#pragma unroll
        for (int nj = 0; nj < 4; nj++) {
            const int w = nw + nj * 8 + (lane & 3) * 2;
            *(float2*)(op0 + w) = make_float2(acc[mi][nj][0] + bv0, acc[mi][nj][1] + bv0);
            *(float2*)(op1 + w) = make_float2(acc[mi][nj][2] + bv1, acc[mi][nj][3] + bv1);
        }
    }
}

// ---------------- conv-branch f ----------------
__global__ __launch_bounds__(256) void conv_f(const float* __restrict__ fc_w) {
    const int flat = blockIdx.x * 256 + threadIdx.x;   // 4*64*2048
    const int w4 = flat & 2047;
    const int dd = (flat >> 11) & 63;
    const int b = flat >> 17;
    float4 acc = make_float4(0.f, 0.f, 0.f, 0.f);
#pragma unroll
    for (int hh = 0; hh < HEADS; hh++) {
        const int ch = hh * HD + dd;
        float cq = __ldg(&fc_w[hh]), ckk = __ldg(&fc_w[4 + hh]), cv = __ldg(&fc_w[8 + hh]);
        const float4 q = *(const float4*)(g_qkv + (((size_t)0 * BATCH + b) * CH + ch) * W_TOT + w4 * 4);
        const float4 k = *(const float4*)(g_qkv + (((size_t)1 * BATCH + b) * CH + ch) * W_TOT + w4 * 4);
        const float4 v = *(const float4*)(g_qkv + (((size_t)2 * BATCH + b) * CH + ch) * W_TOT + w4 * 4);
        acc.x += cq * q.x + ckk * k.x + cv * v.x;
        acc.y += cq * q.y + ckk * k.y + cv * v.y;
        acc.z += cq * q.z + ckk * k.z + cv * v.z;
        acc.w += cq * q.w + ckk * k.w + cv * v.w;
    }
    *(float4*)(g_f + ((size_t)b * HD + dd) * W_TOT + w4 * 4) = acc;
}

// ---------------- attention epilogue (one head per block) ----------------
#define TW 128
#define KSP (TW + 6)  // 134
#define EPI_SMEM ((2 * HD * KSP + 3 * HD) * 4)

__global__ __launch_bounds__(128) void attn_epilogue(
    const float* __restrict__ wp, const float* __restrict__ dep_w,
    const float* __restrict__ dep_b, const float* __restrict__ r1p,
    const float* __restrict__ r2p, float* __restrict__ out) {
    extern __shared__ float sm[];
    float* ks = sm;                     // [64][134]
    float* vs = ks + HD * KSP;          // [64][134]
    float* wps = vs + HD * KSP;         // [64]
    float* sdw = wps + HD;              // [64]
    float* sdb = sdw + HD;              // [64]

    const int b = blockIdx.z, h = blockIdx.y;
    const int w0 = blockIdx.x * TW;
    const int tid = threadIdx.x;

    const float* qg = g_qkv + (((size_t)0 * BATCH + b) * CH + h * HD) * W_TOT;
    const float* kg = g_qkv + (((size_t)1 * BATCH + b) * CH + h * HD) * W_TOT;
    const float* vg = g_qkv + (((size_t)2 * BATCH + b) * CH + h * HD) * W_TOT;

    for (int i = tid; i < HD * KSP; i += 128) {
        int c = i / KSP, j = i % KSP;
        int gp = w0 - PADR + j;
        gp = gp < 0 ? -gp : (gp >= W_TOT ? 2 * W_TOT - 2 - gp : gp);
        ks[i] = kg[(size_t)c * W_TOT + gp];
        vs[i] = vg[(size_t)c * W_TOT + gp];
    }
    if (tid < HD) {
        wps[tid] = wp[tid];
        sdw[tid] = dep_w[h * HD + tid];
        sdb[tid] = dep_b[h * HD + tid];
    }
    __syncthreads();

    const int wl = tid, w = w0 + wl;
    float logit[KATT] = {0.f, 0.f, 0.f, 0.f, 0.f, 0.f, 0.f};
    float qwp = 0.f;
#pragma unroll 8
    for (int d = 0; d < HD; d++) {
        float qd = __ldg(&qg[(size_t)d * W_TOT + w]) * 0.125f;
        qwp += qd * wps[d];
        const float* kp = &ks[d * KSP + wl];
#pragma unroll
        for (int k = 0; k < KATT; k++) logit[k] += qd * kp[k];
    }
    const float inv = 2.0f / (float)(W_TOT - 1);
#pragma unroll
    for (int k = 0; k < KATT; k++) {
        int pos = w + k - PADR;
        int pr = pos < 0 ? -pos : (pos >= W_TOT ? 2 * W_TOT - 2 - pos : pos);
        logit[k] += qwp * inv * (float)(w - pr);
    }
    float m = logit[0];
#pragma unroll
    for (int k = 1; k < KATT; k++) m = fmaxf(m, logit[k]);
    float att[KATT], ssum = 0.f;
#pragma unroll
    for (int k = 0; k < KATT; k++) { att[k] = __expf(logit[k] - m); ssum += att[k]; }
    float rcs = 1.0f / ssum;
#pragma unroll
    for (int k = 0; k < KATT; k++) att[k] *= rcs;

    const float r1 = r1p[0], r2 = r2p[0];
    float* outp = out + ((size_t)b * CH + h * HD) * W_TOT + w;
    float fval = 0.f;
#pragma unroll 8
    for (int d = 0; d < HD; d++) {
        if ((d & 3) == 0)
            fval = __ldg(&g_f[((size_t)b * HD + h * 16 + (d >> 2)) * W_TOT + w]);
        const float* vpp = &vs[d * KSP + wl];
        float oa = 0.f;
#pragma unroll
        for (int k = 0; k < KATT; k++) oa += att[k] * vpp[k];
        outp[(size_t)d * W_TOT] = r1 * oa + r2 * (sdw[d] * fval + sdb[d]);
    }
}

// ---------------- launch ----------------
extern "C" void kernel_launch(void* const* d_in, const int* in_sizes, int n_in,
                              void* d_out, int out_size) {
    const float* x     = (const float*)d_in[0];
    const float* w1    = (const float*)d_in[1];
    const float* b1    = (const float*)d_in[2];
    const float* w2    = (const float*)d_in[3];
    const float* b2    = (const float*)d_in[4];
    const float* w3    = (const float*)d_in[5];
    const float* b3    = (const float*)d_in[6];
    const float* wp    = (const float*)d_in[7];
    // d_in[8] = bp : cancels analytically
    const float* fc_w  = (const float*)d_in[9];
    const float* dep_w = (const float*)d_in[10];
    const float* dep_b = (const float*)d_in[11];
    const float* rate1 = (const float*)d_in[12];
    const float* rate2 = (const float*)d_in[13];
    float* out = (float*)d_out;

    cudaFuncSetAttribute(gemm_mma, cudaFuncAttributeMaxDynamicSharedMemorySize, GEMM_SMEM);
    cudaFuncSetAttribute(attn_epilogue, cudaFuncAttributeMaxDynamicSharedMemorySize, EPI_SMEM);

    transpose_split<<<dim3(W_TOT / 32, CH / 32, BATCH), dim3(32, 8)>>>(x);
    convert_w<<<MROWS, 256>>>(w1, w2, w3);
    gemm_mma<<<dim3(W_TOT / 128, MROWS / 128, BATCH), 256, GEMM_SMEM>>>(b1, b2, b3);
    conv_f<<<(BATCH * HD * (W_TOT / 4)) / 256, 256>>>(fc_w);
    attn_epilogue<<<dim3(W_TOT / TW, HEADS, BATCH), 128, EPI_SMEM>>>(
        wp, dep_w, dep_b, rate1, rate2, out);
}